// round 7
// baseline (speedup 1.0000x reference)
#include <cuda_runtime.h>
#include <cuda_fp16.h>
#include <cstdint>

// Spatial RNN, 4 dirs, R=8 steps, C=64. f16 mma.sync + ldmatrix/stmatrix.
// x:(8,192,192,64) fp32; W_*:(64,64); out:(8,192,192,256)
//
// One CTA per scan line (3072 CTAs x 384 thr = 12 warps). Warp tile: m16 x n64
// (warp w owns rows 16w..16w+15, all 64 cols) -> no A duplication across warps.
// 2 dirs x 8 chained [192,64]x[64,64] GEMMs (mma.sync.m16n8k16.f16, f32 acc).
// Buffers: Xb (converted x, persistent) + P0/P1 ping-pong, 144B row stride
// (conflict-free LDSM/STSM), zero guard rows; 1-row shift folded into LDSM
// addresses. Weights in registers per direction.

#define STRB 144                 // bytes per buffer row (64 f16 + pad)
#define BROWS 194                // rows 0..193, guards at 0 and 193
#define BUFB (BROWS * STRB)      // 27936 bytes
#define SMEM_DYN (3 * BUFB + 64) // 83872

static __device__ __forceinline__ uint32_t smem_u32(const void* p) {
    uint32_t a;
    asm("{ .reg .u64 t; cvta.to.shared.u64 t, %1; cvt.u32.u64 %0, t; }" : "=r"(a) : "l"(p));
    return a;
}
static __device__ __forceinline__ uint32_t pkh2(float lo, float hi) {
    uint32_t r;
    asm("cvt.rn.f16x2.f32 %0, %1, %2;" : "=r"(r) : "f"(hi), "f"(lo));
    return r;
}
static __device__ __forceinline__ void ldsm4(uint32_t a[4], uint32_t addr) {
    asm volatile("ldmatrix.sync.aligned.m8n8.x4.shared.b16 {%0,%1,%2,%3}, [%4];"
                 : "=r"(a[0]), "=r"(a[1]), "=r"(a[2]), "=r"(a[3]) : "r"(addr));
}
static __device__ __forceinline__ void stsm4(uint32_t addr, uint32_t r0, uint32_t r1,
                                             uint32_t r2, uint32_t r3) {
    asm volatile("stmatrix.sync.aligned.m8n8.x4.shared.b16 [%0], {%1,%2,%3,%4};"
                 :: "r"(addr), "r"(r0), "r"(r1), "r"(r2), "r"(r3) : "memory");
}
static __device__ __forceinline__ void mma16816(float c[4], const uint32_t a[4],
                                                const uint32_t b[2]) {
    asm volatile(
        "mma.sync.aligned.m16n8k16.row.col.f32.f16.f16.f32 "
        "{%0,%1,%2,%3}, {%4,%5,%6,%7}, {%8,%9}, {%0,%1,%2,%3};"
        : "+f"(c[0]), "+f"(c[1]), "+f"(c[2]), "+f"(c[3])
        : "r"(a[0]), "r"(a[1]), "r"(a[2]), "r"(a[3]), "r"(b[0]), "r"(b[1]));
}
static __device__ __forceinline__ void sts128(uint32_t addr, uint32_t a, uint32_t b,
                                              uint32_t c, uint32_t d) {
    asm volatile("st.shared.v4.b32 [%0], {%1,%2,%3,%4};"
                 :: "r"(addr), "r"(a), "r"(b), "r"(c), "r"(d) : "memory");
}

extern "C" __global__ void __launch_bounds__(384, 1)
rnn_kernel(const float* __restrict__ x,
           const float* __restrict__ W_left, const float* __restrict__ W_right,
           const float* __restrict__ W_up,   const float* __restrict__ W_down,
           float* __restrict__ out)
{
    extern __shared__ char dsm[];
    const uint32_t base = (smem_u32(dsm) + 15u) & ~15u;
    const uint32_t Xb = base;              // converted x (f16), persistent
    const uint32_t P0 = base + BUFB;       // ping-pong state
    const uint32_t P1 = base + 2 * BUFB;

    const int tid  = threadIdx.x;
    const int lane = tid & 31;
    const int warp = tid >> 5;             // 0..11 = m-group (16 rows each)
    const int gID  = lane >> 2;
    const int tg   = lane & 3;
    const int m0   = warp * 16;

    // --- geometry ---
    long inBase, outBase;
    int pixIn, pixOut, chBase;
    const float *Wfp, *Wbp;
    {
        int l = blockIdx.x;
        if (l < 1536) {                            // horizontal row
            inBase  = (long)l * (192 * 64);
            outBase = (long)l * (192 * 256);
            pixIn = 64;  pixOut = 256;  chBase = 0;
            Wfp = W_left;  Wbp = W_right;
        } else {                                    // vertical column
            int l2 = l - 1536;
            int b = l2 / 192, w = l2 % 192;
            inBase  = (long)b * (192 * 192 * 64)  + (long)w * 64;
            outBase = (long)b * (192 * 192 * 256) + (long)w * 256;
            pixIn = 192 * 64;  pixOut = 192 * 256;  chBase = 128;
            Wfp = W_up;  Wbp = W_down;
        }
    }
    const float* xl = x + inBase;
    float* ol = out + outBase;

    // --- zero guard rows (rows 0 and 193 of all three buffers) ---
    if (tid < 36) {
        asm volatile("st.shared.b32 [%0], %1;" :: "r"(Xb + tid * 4), "r"(0) : "memory");
        asm volatile("st.shared.b32 [%0], %1;" :: "r"(Xb + 193 * STRB + tid * 4), "r"(0) : "memory");
        asm volatile("st.shared.b32 [%0], %1;" :: "r"(P0 + tid * 4), "r"(0) : "memory");
        asm volatile("st.shared.b32 [%0], %1;" :: "r"(P0 + 193 * STRB + tid * 4), "r"(0) : "memory");
        asm volatile("st.shared.b32 [%0], %1;" :: "r"(P1 + tid * 4), "r"(0) : "memory");
        asm volatile("st.shared.b32 [%0], %1;" :: "r"(P1 + 193 * STRB + tid * 4), "r"(0) : "memory");
    }

    // --- load x (f16) into Xb rows 1..192, once for both dirs ---
    #pragma unroll
    for (int p = 0; p < 2; p++) {
        int i = tid + p * 384;                  // 0..767
        int r = i >> 2;
        int c0 = (i & 3) * 16;
        const float* xp = xl + (long)r * pixIn + c0;
        uint32_t h[8];
        #pragma unroll
        for (int j = 0; j < 4; j++) {
            float4 v = *reinterpret_cast<const float4*>(xp + j * 4);
            h[2 * j]     = pkh2(v.x, v.y);
            h[2 * j + 1] = pkh2(v.z, v.w);
        }
        uint32_t a0 = Xb + (r + 1) * STRB + c0 * 2;
        sts128(a0,      h[0], h[1], h[2], h[3]);
        sts128(a0 + 16, h[4], h[5], h[6], h[7]);
    }

    // LDSM/STSM per-thread row/col decomposition:
    //   lanes 0-7 -> mat0 (rows 0-7, colbyte 0), 8-15 -> mat1 (rows 8-15, 0),
    //   16-23 -> mat2 (rows 0-7, colbyte 16), 24-31 -> mat3 (rows 8-15, 16)
    const int lrow = (lane & 7) + ((lane >> 3) & 1) * 8;
    const int lcol = (lane >> 4) * 16;
    const uint32_t stOff = (uint32_t)((m0 + lrow + 1) * STRB + lcol);

    __syncthreads();

    #pragma unroll 1
    for (int dir = 0; dir < 2; dir++) {
        const float* Wg = dir ? Wbp : Wfp;
        const int shift = dir ? 1 : -1;            // fwd reads r-1, bwd reads r+1

        // --- B fragments in registers (f16x2), straight from gmem (L2-hot) ---
        uint32_t b[4][8][2];
        #pragma unroll
        for (int kc = 0; kc < 4; kc++)
            #pragma unroll
            for (int nt = 0; nt < 8; nt++) {
                int k0 = kc * 16 + 2 * tg;
                int n  = nt * 8 + gID;
                b[kc][nt][0] = pkh2(__ldg(&Wg[(k0)     * 64 + n]), __ldg(&Wg[(k0 + 1) * 64 + n]));
                b[kc][nt][1] = pkh2(__ldg(&Wg[(k0 + 8) * 64 + n]), __ldg(&Wg[(k0 + 9) * 64 + n]));
            }

        float acc[8][4];
        #pragma unroll
        for (int nt = 0; nt < 8; nt++)
            #pragma unroll
            for (int e = 0; e < 4; e++) acc[nt][e] = 0.f;

        const uint32_t ldOff = (uint32_t)((m0 + lrow + shift + 1) * STRB + lcol);

        uint32_t src = Xb, dst = P0;

        #pragma unroll 1
        for (int s = 0; s < 8; s++) {
            float Cf[8][4];
            #pragma unroll
            for (int nt = 0; nt < 8; nt++)
                #pragma unroll
                for (int e = 0; e < 4; e++) Cf[nt][e] = 0.f;

            #pragma unroll
            for (int kc = 0; kc < 4; kc++) {
                uint32_t a[4];
                ldsm4(a, src + ldOff + kc * 32);
                #pragma unroll
                for (int nt = 0; nt < 8; nt++)
                    mma16816(Cf[nt], a, b[kc][nt]);
            }

            const bool last = (s == 7);
            uint32_t h[8][2];
            #pragma unroll
            for (int nt = 0; nt < 8; nt++) {
                float v0 = fmaxf(Cf[nt][0], 0.f);
                float v1 = fmaxf(Cf[nt][1], 0.f);
                float v2 = fmaxf(Cf[nt][2], 0.f);
                float v3 = fmaxf(Cf[nt][3], 0.f);
                acc[nt][0] += v0;  acc[nt][1] += v1;
                acc[nt][2] += v2;  acc[nt][3] += v3;
                h[nt][0] = pkh2(v0, v1);
                h[nt][1] = pkh2(v2, v3);
            }
            if (!last) {
                #pragma unroll
                for (int g = 0; g < 4; g++)
                    stsm4(dst + stOff + g * 32,
                          h[2 * g][0], h[2 * g][1], h[2 * g + 1][0], h[2 * g + 1][1]);
                __syncthreads();
            }

            src = dst;
            dst = (dst == P0) ? P1 : P0;
        }

        // --- epilogue: out = x + acc ---
        const int cb = chBase + dir * 64;
        #pragma unroll
        for (int hh = 0; hh < 2; hh++) {
            int gr = m0 + gID + hh * 8;
            const float* xp = xl + (long)gr * pixIn;
            float* op = ol + (long)gr * pixOut + cb;
            #pragma unroll
            for (int nt = 0; nt < 8; nt++) {
                int col = nt * 8 + 2 * tg;
                float2 xv = *reinterpret_cast<const float2*>(xp + col);
                float2 o = make_float2(xv.x + acc[nt][2 * hh],
                                       xv.y + acc[nt][2 * hh + 1]);
                *reinterpret_cast<float2*>(op + col) = o;
            }
        }
        __syncthreads();   // all reads of P0/P1 done before dir 2 reuses them
    }
}

extern "C" void kernel_launch(void* const* d_in, const int* in_sizes, int n_in,
                              void* d_out, int out_size)
{
    const float* x  = (const float*)d_in[0];
    const float* wl = (const float*)d_in[1];
    const float* wr = (const float*)d_in[2];
    const float* wu = (const float*)d_in[3];
    const float* wd = (const float*)d_in[4];
    float* out = (float*)d_out;

    cudaFuncSetAttribute(rnn_kernel, cudaFuncAttributeMaxDynamicSharedMemorySize, SMEM_DYN);
    rnn_kernel<<<3072, 384, SMEM_DYN>>>(x, wl, wr, wu, wd, out);
}

// round 8
// speedup vs baseline: 1.1595x; 1.1595x over previous
#include <cuda_runtime.h>
#include <cuda_fp16.h>
#include <cstdint>

// Spatial RNN, 4 dirs, R=8 steps, C=64. f16 mma.sync + ldmatrix/stmatrix.
// x:(8,192,192,64) fp32; W_*:(64,64); out:(8,192,192,256)
//
// One CTA per scan line (3072 CTAs x 256 thr, 8 warps). Warp tile m48 x n32
// (mg=warp&3 -> 48 rows, ng=warp>>2 -> 32 cols). 2 dirs x 8 chained
// [192,64]x[64,64] GEMMs (mma.sync.m16n8k16.f16, f32 accum).
//
// Latency restructure: A fragments live in registers across steps. After the
// step's STSM, a pair-scoped named barrier (the mg-pair owns 47/48 source
// rows) lets the 8 inner LDSM issue early; the CTA barrier covers only the
// single boundary row (4 edge LDSM). Xb holds converted x for both dirs.

#define STRB 144                 // bytes per buffer row (64 f16 + pad)
#define BROWS 194                // rows 0..193, guards at 0 and 193
#define BUFB (BROWS * STRB)      // 27936 bytes
#define SMEM_DYN (3 * BUFB + 64) // 83872

static __device__ __forceinline__ uint32_t smem_u32(const void* p) {
    uint32_t a;
    asm("{ .reg .u64 t; cvta.to.shared.u64 t, %1; cvt.u32.u64 %0, t; }" : "=r"(a) : "l"(p));
    return a;
}
static __device__ __forceinline__ uint32_t pkh2(float lo, float hi) {
    uint32_t r;
    asm("cvt.rn.f16x2.f32 %0, %1, %2;" : "=r"(r) : "f"(hi), "f"(lo));
    return r;
}
static __device__ __forceinline__ void ldsm4(uint32_t a[4], uint32_t addr) {
    asm volatile("ldmatrix.sync.aligned.m8n8.x4.shared.b16 {%0,%1,%2,%3}, [%4];"
                 : "=r"(a[0]), "=r"(a[1]), "=r"(a[2]), "=r"(a[3]) : "r"(addr));
}
static __device__ __forceinline__ void stsm4(uint32_t addr, uint32_t r0, uint32_t r1,
                                             uint32_t r2, uint32_t r3) {
    asm volatile("stmatrix.sync.aligned.m8n8.x4.shared.b16 [%0], {%1,%2,%3,%4};"
                 :: "r"(addr), "r"(r0), "r"(r1), "r"(r2), "r"(r3) : "memory");
}
static __device__ __forceinline__ void mma16816(float c[4], const uint32_t a[4],
                                                const uint32_t b[2]) {
    asm volatile(
        "mma.sync.aligned.m16n8k16.row.col.f32.f16.f16.f32 "
        "{%0,%1,%2,%3}, {%4,%5,%6,%7}, {%8,%9}, {%0,%1,%2,%3};"
        : "+f"(c[0]), "+f"(c[1]), "+f"(c[2]), "+f"(c[3])
        : "r"(a[0]), "r"(a[1]), "r"(a[2]), "r"(a[3]), "r"(b[0]), "r"(b[1]));
}
static __device__ __forceinline__ void sts128(uint32_t addr, uint32_t a, uint32_t b,
                                              uint32_t c, uint32_t d) {
    asm volatile("st.shared.v4.b32 [%0], {%1,%2,%3,%4};"
                 :: "r"(addr), "r"(a), "r"(b), "r"(c), "r"(d) : "memory");
}
static __device__ __forceinline__ void barn(int id) {   // named barrier, 64 threads
    asm volatile("bar.sync %0, 64;" :: "r"(id) : "memory");
}

extern "C" __global__ void __launch_bounds__(256, 1)
rnn_kernel(const float* __restrict__ x,
           const float* __restrict__ W_left, const float* __restrict__ W_right,
           const float* __restrict__ W_up,   const float* __restrict__ W_down,
           float* __restrict__ out)
{
    extern __shared__ char dsm[];
    const uint32_t base = (smem_u32(dsm) + 15u) & ~15u;
    const uint32_t Xb = base;
    const uint32_t P0 = base + BUFB;
    const uint32_t P1 = base + 2 * BUFB;

    const int tid  = threadIdx.x;
    const int lane = tid & 31;
    const int warp = tid >> 5;
    const int mg   = warp & 3;        // 4 m-groups of 48 rows
    const int ng   = warp >> 2;       // 2 n-groups of 32 cols
    const int gID  = lane >> 2;
    const int tg   = lane & 3;
    const int m0   = mg * 48;
    const int n0   = ng * 32;

    // --- geometry ---
    long inBase, outBase;
    int pixIn, pixOut, chBase;
    const float *Wfp, *Wbp;
    {
        int l = blockIdx.x;
        if (l < 1536) {                            // horizontal row
            inBase  = (long)l * (192 * 64);
            outBase = (long)l * (192 * 256);
            pixIn = 64;  pixOut = 256;  chBase = 0;
            Wfp = W_left;  Wbp = W_right;
        } else {                                    // vertical column
            int l2 = l - 1536;
            int b = l2 / 192, w = l2 % 192;
            inBase  = (long)b * (192 * 192 * 64)  + (long)w * 64;
            outBase = (long)b * (192 * 192 * 256) + (long)w * 256;
            pixIn = 192 * 64;  pixOut = 192 * 256;  chBase = 128;
            Wfp = W_up;  Wbp = W_down;
        }
    }
    const float* xl = x + inBase;
    float* ol = out + outBase;

    // --- zero guard rows (rows 0 and 193 of all three buffers) ---
    if (tid < 36) {
        asm volatile("st.shared.b32 [%0], %1;" :: "r"(Xb + tid * 4), "r"(0) : "memory");
        asm volatile("st.shared.b32 [%0], %1;" :: "r"(Xb + 193 * STRB + tid * 4), "r"(0) : "memory");
        asm volatile("st.shared.b32 [%0], %1;" :: "r"(P0 + tid * 4), "r"(0) : "memory");
        asm volatile("st.shared.b32 [%0], %1;" :: "r"(P0 + 193 * STRB + tid * 4), "r"(0) : "memory");
        asm volatile("st.shared.b32 [%0], %1;" :: "r"(P1 + tid * 4), "r"(0) : "memory");
        asm volatile("st.shared.b32 [%0], %1;" :: "r"(P1 + 193 * STRB + tid * 4), "r"(0) : "memory");
    }

    // --- load x (f16) into Xb rows 1..192 (once, both dirs use it) ---
    #pragma unroll
    for (int p = 0; p < 3; p++) {
        int i = tid + p * 256;                  // 0..767
        int r = i >> 2;
        int c0 = (i & 3) * 16;
        const float* xp = xl + (long)r * pixIn + c0;
        uint32_t h[8];
        #pragma unroll
        for (int j = 0; j < 4; j++) {
            float4 v = *reinterpret_cast<const float4*>(xp + j * 4);
            h[2 * j]     = pkh2(v.x, v.y);
            h[2 * j + 1] = pkh2(v.z, v.w);
        }
        uint32_t a0 = Xb + (r + 1) * STRB + c0 * 2;
        sts128(a0,      h[0], h[1], h[2], h[3]);
        sts128(a0 + 16, h[4], h[5], h[6], h[7]);
    }

    // LDSM/STSM per-thread row/col decomposition
    const int lrow = (lane & 7) + ((lane >> 3) & 1) * 8;
    const int lcol = (lane >> 4) * 16;
    const uint32_t stOff = (uint32_t)((m0 + lrow + 1) * STRB + lcol);
    const int pairBar = mg + 1;       // named barrier per mg-pair (ids 1..4)

    __syncthreads();

    #pragma unroll
    for (int dir = 0; dir < 2; dir++) {
        const float* Wg = dir ? Wbp : Wfp;
        const int shift = dir ? 1 : -1;            // fwd reads r-1, bwd reads r+1

        // --- B fragments in registers (f16x2), from gmem (L2-hot) ---
        uint32_t b[4][4][2];
        #pragma unroll
        for (int kc = 0; kc < 4; kc++)
            #pragma unroll
            for (int nt = 0; nt < 4; nt++) {
                int k0 = kc * 16 + 2 * tg;
                int n  = n0 + nt * 8 + gID;
                b[kc][nt][0] = pkh2(__ldg(&Wg[(k0)     * 64 + n]), __ldg(&Wg[(k0 + 1) * 64 + n]));
                b[kc][nt][1] = pkh2(__ldg(&Wg[(k0 + 8) * 64 + n]), __ldg(&Wg[(k0 + 9) * 64 + n]));
            }

        float acc[3][4][4];
        #pragma unroll
        for (int mt = 0; mt < 3; mt++)
            #pragma unroll
            for (int nt = 0; nt < 4; nt++)
                #pragma unroll
                for (int e = 0; e < 4; e++) acc[mt][nt][e] = 0.f;

        const uint32_t ldOff = (uint32_t)((m0 + lrow + shift + 1) * STRB + lcol);

        // --- prologue: A fragments from Xb ---
        uint32_t a[3][4][4];
        #pragma unroll
        for (int mt = 0; mt < 3; mt++)
            #pragma unroll
            for (int kc = 0; kc < 4; kc++)
                ldsm4(a[mt][kc], Xb + ldOff + mt * (16 * STRB) + kc * 32);

        uint32_t dst = P0;

        #pragma unroll 1
        for (int s = 0; s < 8; s++) {
            float Cf[3][4][4];
            #pragma unroll
            for (int mt = 0; mt < 3; mt++)
                #pragma unroll
                for (int nt = 0; nt < 4; nt++)
                    #pragma unroll
                    for (int e = 0; e < 4; e++) Cf[mt][nt][e] = 0.f;

            #pragma unroll
            for (int kc = 0; kc < 4; kc++)
                #pragma unroll
                for (int mt = 0; mt < 3; mt++)
                    #pragma unroll
                    for (int nt = 0; nt < 4; nt++)
                        mma16816(Cf[mt][nt], a[mt][kc], b[kc][nt]);

            const bool last = (s == 7);

            // tail: relu, accumulate, pack, store state
            #pragma unroll
            for (int mt = 0; mt < 3; mt++) {
                uint32_t h[4][2];
                #pragma unroll
                for (int nt = 0; nt < 4; nt++) {
                    float v0 = fmaxf(Cf[mt][nt][0], 0.f);
                    float v1 = fmaxf(Cf[mt][nt][1], 0.f);
                    float v2 = fmaxf(Cf[mt][nt][2], 0.f);
                    float v3 = fmaxf(Cf[mt][nt][3], 0.f);
                    acc[mt][nt][0] += v0;  acc[mt][nt][1] += v1;
                    acc[mt][nt][2] += v2;  acc[mt][nt][3] += v3;
                    h[nt][0] = pkh2(v0, v1);
                    h[nt][1] = pkh2(v2, v3);
                }
                if (!last) {
                    uint32_t sa = dst + stOff + mt * (16 * STRB) + n0 * 2;
                    stsm4(sa,      h[0][0], h[0][1], h[1][0], h[1][1]);
                    stsm4(sa + 32, h[2][0], h[2][1], h[3][0], h[3][1]);
                }
            }

            if (!last) {
                // pair barrier: mg-pair's stores visible -> inner rows ready
                barn(pairBar);
                if (dir == 0) {    // shift -1: edge = mt0 (row m0-1), inner mt1,mt2
                    #pragma unroll
                    for (int kc = 0; kc < 4; kc++) ldsm4(a[1][kc], dst + ldOff + 1 * (16 * STRB) + kc * 32);
                    #pragma unroll
                    for (int kc = 0; kc < 4; kc++) ldsm4(a[2][kc], dst + ldOff + 2 * (16 * STRB) + kc * 32);
                    __syncthreads();
                    #pragma unroll
                    for (int kc = 0; kc < 4; kc++) ldsm4(a[0][kc], dst + ldOff + 0 * (16 * STRB) + kc * 32);
                } else {           // shift +1: edge = mt2 (row m0+48), inner mt0,mt1
                    #pragma unroll
                    for (int kc = 0; kc < 4; kc++) ldsm4(a[0][kc], dst + ldOff + 0 * (16 * STRB) + kc * 32);
                    #pragma unroll
                    for (int kc = 0; kc < 4; kc++) ldsm4(a[1][kc], dst + ldOff + 1 * (16 * STRB) + kc * 32);
                    __syncthreads();
                    #pragma unroll
                    for (int kc = 0; kc < 4; kc++) ldsm4(a[2][kc], dst + ldOff + 2 * (16 * STRB) + kc * 32);
                }
                dst = (dst == P0) ? P1 : P0;
            }
        }

        // --- epilogue: out = x + acc ---
        const int cb = chBase + dir * 64;
        #pragma unroll
        for (int mt = 0; mt < 3; mt++) {
            #pragma unroll
            for (int hh = 0; hh < 2; hh++) {
                int gr = m0 + mt * 16 + gID + hh * 8;
                const float* xp = xl + (long)gr * pixIn;
                float* op = ol + (long)gr * pixOut + cb;
                #pragma unroll
                for (int nt = 0; nt < 4; nt++) {
                    int col = n0 + nt * 8 + 2 * tg;
                    float2 xv = *reinterpret_cast<const float2*>(xp + col);
                    float2 o = make_float2(xv.x + acc[mt][nt][2 * hh],
                                           xv.y + acc[mt][nt][2 * hh + 1]);
                    *reinterpret_cast<float2*>(op + col) = o;
                }
            }
        }
        __syncthreads();   // all P0/P1 reads done before next dir reuses them
    }
}

extern "C" void kernel_launch(void* const* d_in, const int* in_sizes, int n_in,
                              void* d_out, int out_size)
{
    const float* x  = (const float*)d_in[0];
    const float* wl = (const float*)d_in[1];
    const float* wr = (const float*)d_in[2];
    const float* wu = (const float*)d_in[3];
    const float* wd = (const float*)d_in[4];
    float* out = (float*)d_out;

    cudaFuncSetAttribute(rnn_kernel, cudaFuncAttributeMaxDynamicSharedMemorySize, SMEM_DYN);
    rnn_kernel<<<3072, 256, SMEM_DYN>>>(x, wl, wr, wu, wd, out);
}

// round 9
// speedup vs baseline: 1.4883x; 1.2836x over previous
#include <cuda_runtime.h>
#include <cuda_fp16.h>
#include <cstdint>

// Spatial RNN, 4 dirs, R=8 steps, C=64. f16 mma.sync (f16 accum) + LDSM/STSM.
// x:(8,192,192,64) fp32; W_*:(64,64); out:(8,192,192,256)
//
// One CTA per scan line (3072 CTAs x 256 thr, 8 warps, m48xn32 warp tiles).
// 2 dirs x 8 chained [192,64]x[64,64] GEMMs. Cf/acc are packed f16x2 ->
// ~120 regs -> 2 CTAs/SM; tail is 4 packed ops per (mt,nt). Buffers: Xb
// (persistent f16 x) + P0/P1 ping-pong, 144B stride, zero guard rows,
// shift folded into LDSM addresses. Weights in registers per direction.

#define STRB 144                 // bytes per buffer row (64 f16 + pad)
#define BROWS 194                // rows 0..193, guards at 0 and 193
#define BUFB (BROWS * STRB)      // 27936 bytes
#define SMEM_DYN (3 * BUFB + 64) // 83872

static __device__ __forceinline__ uint32_t smem_u32(const void* p) {
    uint32_t a;
    asm("{ .reg .u64 t; cvta.to.shared.u64 t, %1; cvt.u32.u64 %0, t; }" : "=r"(a) : "l"(p));
    return a;
}
static __device__ __forceinline__ uint32_t pkh2(float lo, float hi) {
    uint32_t r;
    asm("cvt.rn.f16x2.f32 %0, %1, %2;" : "=r"(r) : "f"(hi), "f"(lo));
    return r;
}
static __device__ __forceinline__ uint32_t hmax2z(uint32_t v) {
    uint32_t r;
    asm("max.f16x2 %0, %1, %2;" : "=r"(r) : "r"(v), "r"(0u));
    return r;
}
static __device__ __forceinline__ uint32_t hadd2(uint32_t a, uint32_t b) {
    uint32_t r;
    asm("add.f16x2 %0, %1, %2;" : "=r"(r) : "r"(a), "r"(b));
    return r;
}
static __device__ __forceinline__ void unpkh2(uint32_t v, float& lo, float& hi) {
    asm("{ .reg .f16 l, h; mov.b32 {l, h}, %2; cvt.f32.f16 %0, l; cvt.f32.f16 %1, h; }"
        : "=f"(lo), "=f"(hi) : "r"(v));
}
static __device__ __forceinline__ void ldsm4(uint32_t a[4], uint32_t addr) {
    asm volatile("ldmatrix.sync.aligned.m8n8.x4.shared.b16 {%0,%1,%2,%3}, [%4];"
                 : "=r"(a[0]), "=r"(a[1]), "=r"(a[2]), "=r"(a[3]) : "r"(addr));
}
static __device__ __forceinline__ void stsm4(uint32_t addr, uint32_t r0, uint32_t r1,
                                             uint32_t r2, uint32_t r3) {
    asm volatile("stmatrix.sync.aligned.m8n8.x4.shared.b16 [%0], {%1,%2,%3,%4};"
                 :: "r"(addr), "r"(r0), "r"(r1), "r"(r2), "r"(r3) : "memory");
}
static __device__ __forceinline__ void mma16816h(uint32_t c[2], const uint32_t a[4],
                                                 const uint32_t b[2]) {
    asm volatile(
        "mma.sync.aligned.m16n8k16.row.col.f16.f16.f16.f16 "
        "{%0,%1}, {%2,%3,%4,%5}, {%6,%7}, {%0,%1};"
        : "+r"(c[0]), "+r"(c[1])
        : "r"(a[0]), "r"(a[1]), "r"(a[2]), "r"(a[3]), "r"(b[0]), "r"(b[1]));
}
static __device__ __forceinline__ void sts128(uint32_t addr, uint32_t a, uint32_t b,
                                              uint32_t c, uint32_t d) {
    asm volatile("st.shared.v4.b32 [%0], {%1,%2,%3,%4};"
                 :: "r"(addr), "r"(a), "r"(b), "r"(c), "r"(d) : "memory");
}

extern "C" __global__ void __launch_bounds__(256, 2)
rnn_kernel(const float* __restrict__ x,
           const float* __restrict__ W_left, const float* __restrict__ W_right,
           const float* __restrict__ W_up,   const float* __restrict__ W_down,
           float* __restrict__ out)
{
    extern __shared__ char dsm[];
    const uint32_t base = (smem_u32(dsm) + 15u) & ~15u;
    const uint32_t Xb = base;              // persistent f16 x
    const uint32_t P0 = base + BUFB;       // ping-pong state
    const uint32_t P1 = base + 2 * BUFB;

    const int tid  = threadIdx.x;
    const int lane = tid & 31;
    const int warp = tid >> 5;
    const int mg   = warp & 3;        // 4 m-groups of 48 rows
    const int ng   = warp >> 2;       // 2 n-groups of 32 cols
    const int gID  = lane >> 2;
    const int tg   = lane & 3;
    const int m0   = mg * 48;
    const int n0   = ng * 32;

    // --- geometry ---
    long inBase, outBase;
    int pixIn, pixOut, chBase;
    const float *Wfp, *Wbp;
    {
        int l = blockIdx.x;
        if (l < 1536) {                            // horizontal row
            inBase  = (long)l * (192 * 64);
            outBase = (long)l * (192 * 256);
            pixIn = 64;  pixOut = 256;  chBase = 0;
            Wfp = W_left;  Wbp = W_right;
        } else {                                    // vertical column
            int l2 = l - 1536;
            int b = l2 / 192, w = l2 % 192;
            inBase  = (long)b * (192 * 192 * 64)  + (long)w * 64;
            outBase = (long)b * (192 * 192 * 256) + (long)w * 256;
            pixIn = 192 * 64;  pixOut = 192 * 256;  chBase = 128;
            Wfp = W_up;  Wbp = W_down;
        }
    }
    const float* xl = x + inBase;
    float* ol = out + outBase;

    // --- zero guard rows (rows 0 and 193 of all three buffers) ---
    if (tid < 36) {
        asm volatile("st.shared.b32 [%0], %1;" :: "r"(Xb + tid * 4), "r"(0) : "memory");
        asm volatile("st.shared.b32 [%0], %1;" :: "r"(Xb + 193 * STRB + tid * 4), "r"(0) : "memory");
        asm volatile("st.shared.b32 [%0], %1;" :: "r"(P0 + tid * 4), "r"(0) : "memory");
        asm volatile("st.shared.b32 [%0], %1;" :: "r"(P0 + 193 * STRB + tid * 4), "r"(0) : "memory");
        asm volatile("st.shared.b32 [%0], %1;" :: "r"(P1 + tid * 4), "r"(0) : "memory");
        asm volatile("st.shared.b32 [%0], %1;" :: "r"(P1 + 193 * STRB + tid * 4), "r"(0) : "memory");
    }

    // --- load x (f16) into Xb rows 1..192 (once; both dirs start here) ---
    #pragma unroll
    for (int p = 0; p < 3; p++) {
        int i = tid + p * 256;                  // 0..767
        int r = i >> 2;
        int c0 = (i & 3) * 16;
        const float* xp = xl + (long)r * pixIn + c0;
        uint32_t h[8];
        #pragma unroll
        for (int j = 0; j < 4; j++) {
            float4 v = *reinterpret_cast<const float4*>(xp + j * 4);
            h[2 * j]     = pkh2(v.x, v.y);
            h[2 * j + 1] = pkh2(v.z, v.w);
        }
        uint32_t a0 = Xb + (r + 1) * STRB + c0 * 2;
        sts128(a0,      h[0], h[1], h[2], h[3]);
        sts128(a0 + 16, h[4], h[5], h[6], h[7]);
    }

    // LDSM/STSM per-thread row/col decomposition
    const int lrow = (lane & 7) + ((lane >> 3) & 1) * 8;
    const int lcol = (lane >> 4) * 16;
    const uint32_t stOff = (uint32_t)((m0 + lrow + 1) * STRB + lcol);

    __syncthreads();

    #pragma unroll 1
    for (int dir = 0; dir < 2; dir++) {
        const float* Wg = dir ? Wbp : Wfp;
        const int shift = dir ? 1 : -1;            // fwd reads r-1, bwd reads r+1

        // --- B fragments in registers (f16x2), from gmem (L2-hot) ---
        uint32_t b[4][4][2];
        #pragma unroll
        for (int kc = 0; kc < 4; kc++)
            #pragma unroll
            for (int nt = 0; nt < 4; nt++) {
                int k0 = kc * 16 + 2 * tg;
                int n  = n0 + nt * 8 + gID;
                b[kc][nt][0] = pkh2(__ldg(&Wg[(k0)     * 64 + n]), __ldg(&Wg[(k0 + 1) * 64 + n]));
                b[kc][nt][1] = pkh2(__ldg(&Wg[(k0 + 8) * 64 + n]), __ldg(&Wg[(k0 + 9) * 64 + n]));
            }

        uint32_t acc[3][4][2];                     // packed f16x2 accumulators
        #pragma unroll
        for (int mt = 0; mt < 3; mt++)
            #pragma unroll
            for (int nt = 0; nt < 4; nt++) {
                acc[mt][nt][0] = 0u;  acc[mt][nt][1] = 0u;
            }

        const uint32_t ldOff = (uint32_t)((m0 + lrow + shift + 1) * STRB + lcol);

        uint32_t src = Xb, dst = P0;

        #pragma unroll 1
        for (int s = 0; s < 8; s++) {
            const bool last = (s == 7);

            #pragma unroll
            for (int mt = 0; mt < 3; mt++) {
                uint32_t a[4][4];
                #pragma unroll
                for (int kc = 0; kc < 4; kc++)
                    ldsm4(a[kc], src + ldOff + mt * (16 * STRB) + kc * 32);

                uint32_t Cf[4][2];
                #pragma unroll
                for (int nt = 0; nt < 4; nt++) { Cf[nt][0] = 0u; Cf[nt][1] = 0u; }

                #pragma unroll
                for (int kc = 0; kc < 4; kc++)
                    #pragma unroll
                    for (int nt = 0; nt < 4; nt++)
                        mma16816h(Cf[nt], a[kc], b[kc][nt]);

                uint32_t h[4][2];
                #pragma unroll
                for (int nt = 0; nt < 4; nt++) {
                    h[nt][0] = hmax2z(Cf[nt][0]);       // relu (packed)
                    h[nt][1] = hmax2z(Cf[nt][1]);
                    acc[mt][nt][0] = hadd2(acc[mt][nt][0], h[nt][0]);
                    acc[mt][nt][1] = hadd2(acc[mt][nt][1], h[nt][1]);
                }
                if (!last) {
                    uint32_t sa = dst + stOff + mt * (16 * STRB) + n0 * 2;
                    stsm4(sa,      h[0][0], h[0][1], h[1][0], h[1][1]);
                    stsm4(sa + 32, h[2][0], h[2][1], h[3][0], h[3][1]);
                }
            }

            if (!last) __syncthreads();
            src = dst;
            dst = (dst == P0) ? P1 : P0;
        }

        // --- epilogue: out = x + acc ---
        const int cb = chBase + dir * 64;
        #pragma unroll
        for (int mt = 0; mt < 3; mt++) {
            #pragma unroll
            for (int hh = 0; hh < 2; hh++) {
                int gr = m0 + mt * 16 + gID + hh * 8;
                const float* xp = xl + (long)gr * pixIn;
                float* op = ol + (long)gr * pixOut + cb;
                #pragma unroll
                for (int nt = 0; nt < 4; nt++) {
                    int col = n0 + nt * 8 + 2 * tg;
                    float a0, a1;
                    unpkh2(acc[mt][nt][hh], a0, a1);
                    float2 xv = *reinterpret_cast<const float2*>(xp + col);
                    float2 o = make_float2(xv.x + a0, xv.y + a1);
                    *reinterpret_cast<float2*>(op + col) = o;
                }
            }
        }
        __syncthreads();   // all P0/P1 reads done before next dir reuses them
    }
}

extern "C" void kernel_launch(void* const* d_in, const int* in_sizes, int n_in,
                              void* d_out, int out_size)
{
    const float* x  = (const float*)d_in[0];
    const float* wl = (const float*)d_in[1];
    const float* wr = (const float*)d_in[2];
    const float* wu = (const float*)d_in[3];
    const float* wd = (const float*)d_in[4];
    float* out = (float*)d_out;

    cudaFuncSetAttribute(rnn_kernel, cudaFuncAttributeMaxDynamicSharedMemorySize, SMEM_DYN);
    rnn_kernel<<<3072, 256, SMEM_DYN>>>(x, wl, wr, wu, wd, out);
}